// round 6
// baseline (speedup 1.0000x reference)
#include <cuda_runtime.h>

typedef unsigned long long ull;

// ---------------- shared weight image ----------------
// 8 row-groups (group g = rows 4g..4g+3, owned by lane rg=g of each column).
// NH row = 76 floats = 19 chunks(16B): [Whh 8ch | (b,0,0,0) | Wih_s 8ch | Wih_a 2ch]
//   group stride = 4*76+4 floats = 308 floats = 77 chunks; 77 mod 8 = 5 ->
//   the 8 lane addresses hit 8 distinct 16B bank-groups: conflict-free.
// M row = 36 floats = 9 chunks: [w 8ch | (b,0,0,0)]
//   group stride = 4*36+4 = 148 floats = 37 chunks; 37 mod 8 = 5 -> conflict-free.
#define NH_FLOATS (8*308)                  // 2464
#define M_FLOATS  (8*148)                  // 1184
#define FC1_OFF   NH_FLOATS                // 2464
#define MEAN_OFF  (FC1_OFF + M_FLOATS)     // 3648
#define STD_OFF   (MEAN_OFF + M_FLOATS)    // 4832
#define W_FLOATS  (STD_OFF + M_FLOATS)     // 6016 floats = 24064 B

// activation slots (per CTA, 16 elements):
// NHV[e] = 17 chunks: [h 0..7 | ONE at 8 | s 9..16]   (a stays in registers)
// MV[e]  =  9 chunks: [hid 0..7 | ONE at 8]
#define NHV_STRIDE 17
#define MV_STRIDE  9

union F4U { float4 f; ulonglong2 u; };

__device__ __forceinline__ ull pack2(float lo, float hi){
  ull r; asm("mov.b64 %0, {%1,%2};" : "=l"(r) : "f"(lo), "f"(hi)); return r;
}
__device__ __forceinline__ float2 unpack2(ull v){
  float2 r; asm("mov.b64 {%0,%1}, %2;" : "=f"(r.x), "=f"(r.y) : "l"(v)); return r;
}
__device__ __forceinline__ ull fma2(ull a, ull b, ull c){
  ull d; asm("fma.rn.f32x2 %0, %1, %2, %3;" : "=l"(d) : "l"(a), "l"(b), "l"(c)); return d;
}
__device__ __forceinline__ float hsum(ull a){ float2 f = unpack2(a); return f.x + f.y; }
__device__ __forceinline__ float tanh_approx(float x){
  float y; asm("tanh.approx.f32 %0, %1;" : "=f"(y) : "f"(x)); return y;
}
__device__ __forceinline__ float softplus_fast(float x){
  float e = __expf(-fabsf(x));
  return fmaxf(x, 0.0f) + __logf(1.0f + e);
}
__device__ __forceinline__ ulonglong2 pack4(const float* y){
  ulonglong2 r; r.x = pack2(y[0],y[1]); r.y = pack2(y[2],y[3]); return r;
}

__global__ void __launch_bounds__(64, 7)
rssm_kernel(const float* __restrict__ s0, const float* __restrict__ h0,
            const float* __restrict__ actions,
            const float* __restrict__ W_ih, const float* __restrict__ W_hh,
            const float* __restrict__ b_ih, const float* __restrict__ b_hh,
            const float* __restrict__ fc1_w, const float* __restrict__ fc1_b,
            const float* __restrict__ mean_w, const float* __restrict__ mean_b,
            const float* __restrict__ std_w, const float* __restrict__ std_b,
            float* __restrict__ out, int B, int T, int n_steps)
{
  __shared__ __align__(16) float sw[W_FLOATS];
  __shared__ __align__(16) ulonglong2 nhv[16*NHV_STRIDE];
  __shared__ __align__(16) ulonglong2 mv [16*MV_STRIDE];
  const int tid = threadIdx.x;

  // ---- stage weights ----
  for (int i=tid;i<W_FLOATS;i+=64) sw[i]=0.0f;
  __syncthreads();
  for (int i=tid;i<32*32;i+=64){
    int j=i>>5,k=i&31; int base=(j>>2)*308+(j&3)*76;
    sw[base+k]=W_hh[i];
  }
  for (int i=tid;i<32*40;i+=64){
    int j=i/40,k=i-j*40; int base=(j>>2)*308+(j&3)*76;
    if (k<32) sw[base+36+k]=W_ih[i]; else sw[base+68+(k-32)]=W_ih[i];
  }
  for (int i=tid;i<32*32;i+=64){
    int j=i>>5,k=i&31; int mb=(j>>2)*148+(j&3)*36;
    sw[FC1_OFF +mb+k]=fc1_w[i];
    sw[MEAN_OFF+mb+k]=mean_w[i];
    sw[STD_OFF +mb+k]=std_w[i];
  }
  if (tid<32){
    int j=tid; int nb=(j>>2)*308+(j&3)*76; int mb=(j>>2)*148+(j&3)*36;
    sw[nb+32]          = b_ih[j]+b_hh[j];
    sw[FC1_OFF +mb+32] = fc1_b[j];
    sw[MEAN_OFF+mb+32] = mean_b[j];
    sw[STD_OFF +mb+32] = std_b[j];
  }
  // seed activation slots: h0 -> chunks 0..7, s0 -> chunks 9..16, ONE chunks
  for (int i=tid;i<16*8;i+=64){
    int e=i>>3, q=i&7; size_t g=(size_t)(blockIdx.x*16+e)*32;
    F4U hv; hv.f=((const float4*)(h0+g))[q];
    F4U sv; sv.f=((const float4*)(s0+g))[q];
    ulonglong2 hc; hc.x=hv.u.x; hc.y=hv.u.y;
    ulonglong2 sc; sc.x=sv.u.x; sc.y=sv.u.y;
    nhv[e*NHV_STRIDE + q]     = hc;
    nhv[e*NHV_STRIDE + 9 + q] = sc;
  }
  if (tid<16){
    ulonglong2 one; one.x=pack2(1.0f,0.0f); one.y=0ull;
    nhv[tid*NHV_STRIDE+8]=one;
    mv [tid*MV_STRIDE +8]=one;
  }
  __syncthreads();

  const int warp = tid>>5;
  const int lane = tid&31;
  const int col  = lane>>3;                 // element column 0..3
  const int rg   = lane&7;                  // row group: rows 4rg..4rg+3
  const int eA   = warp*8 + col;
  const int eB   = eA + 4;
  const int gA   = blockIdx.x*16 + eA;
  const int gB   = blockIdx.x*16 + eB;

  const ulonglong2* nhw = (const ulonglong2*)sw              + rg*77;
  const ulonglong2* f1w = (const ulonglong2*)(sw+FC1_OFF)    + rg*37;
  const ulonglong2* mnw = (const ulonglong2*)(sw+MEAN_OFF)   + rg*37;
  const ulonglong2* sdw = (const ulonglong2*)(sw+STD_OFF)    + rg*37;
  ulonglong2* vA = nhv + eA*NHV_STRIDE;
  ulonglong2* vB = nhv + eB*NHV_STRIDE;
  ulonglong2* uA = mv  + eA*MV_STRIDE;
  ulonglong2* uB = mv  + eB*MV_STRIDE;

  // actions in registers (packed pairs); all 8 lanes of a column load the same
  // address (broadcast-coalesced)
  ull aA[4], aB[4];
  {
    const float4* pA=(const float4*)(actions + (size_t)gA*T*8);
    const float4* pB=(const float4*)(actions + (size_t)gB*T*8);
    F4U x0,x1,y0,y1; x0.f=pA[0]; x1.f=pA[1]; y0.f=pB[0]; y1.f=pB[1];
    aA[0]=x0.u.x; aA[1]=x0.u.y; aA[2]=x1.u.x; aA[3]=x1.u.y;
    aB[0]=y0.u.x; aB[1]=y0.u.y; aB[2]=y1.u.x; aB[3]=y1.u.y;
  }

  for (int t=0;t<n_steps;t++){
    // prefetch next actions
    F4U nA0,nA1,nB0,nB1;
    nA0.u.x=0ull; nA0.u.y=0ull; nA1.u.x=0ull; nA1.u.y=0ull;
    nB0.u.x=0ull; nB0.u.y=0ull; nB1.u.x=0ull; nB1.u.y=0ull;
    if (t+1<n_steps){
      const float4* pA=(const float4*)(actions + ((size_t)gA*T + t+1)*8);
      const float4* pB=(const float4*)(actions + ((size_t)gB*T + t+1)*8);
      nA0.f=pA[0]; nA1.f=pA[1]; nB0.f=pB[0]; nB1.f=pB[1];
    }

    // ================= NH: rows 4rg..4rg+3 of tanh(W@[h,1,s,a]) =================
    ull cA[4], cB[4];
#pragma unroll
    for (int r=0;r<4;r++){ cA[r]=0ull; cB[r]=0ull; }
#pragma unroll
    for (int p=0;p<17;p++){
      ulonglong2 xa = vA[p];
      ulonglong2 xb = vB[p];
#pragma unroll
      for (int r=0;r<4;r++){
        ulonglong2 w = nhw[r*19 + p];
        cA[r]=fma2(w.x,xa.x,cA[r]); cA[r]=fma2(w.y,xa.y,cA[r]);
        cB[r]=fma2(w.x,xb.x,cB[r]); cB[r]=fma2(w.y,xb.y,cB[r]);
      }
    }
#pragma unroll
    for (int pi=0;pi<2;pi++){       // action part from registers
#pragma unroll
      for (int r=0;r<4;r++){
        ulonglong2 w = nhw[r*19 + 17 + pi];
        cA[r]=fma2(w.x,aA[2*pi],cA[r]);   cA[r]=fma2(w.y,aA[2*pi+1],cA[r]);
        cB[r]=fma2(w.x,aB[2*pi],cB[r]);   cB[r]=fma2(w.y,aB[2*pi+1],cB[r]);
      }
    }
    float yhA[4], yhB[4];
#pragma unroll
    for (int r=0;r<4;r++){ yhA[r]=tanh_approx(hsum(cA[r])); yhB[r]=tanh_approx(hsum(cB[r])); }
    __syncwarp();                    // all lanes done reading old h/s
    vA[rg]=pack4(yhA);
    vB[rg]=pack4(yhB);
    __syncwarp();                    // new h visible

    // ================= FC1: hid = elu(W@[h,1]) =================
#pragma unroll
    for (int r=0;r<4;r++){ cA[r]=0ull; cB[r]=0ull; }
#pragma unroll
    for (int p=0;p<9;p++){
      ulonglong2 xa = vA[p];
      ulonglong2 xb = vB[p];
#pragma unroll
      for (int r=0;r<4;r++){
        ulonglong2 w = f1w[r*9 + p];
        cA[r]=fma2(w.x,xa.x,cA[r]); cA[r]=fma2(w.y,xa.y,cA[r]);
        cB[r]=fma2(w.x,xb.x,cB[r]); cB[r]=fma2(w.y,xb.y,cB[r]);
      }
    }
    float yfA[4], yfB[4];
#pragma unroll
    for (int r=0;r<4;r++){
      float x=hsum(cA[r]); yfA[r]= x>0.0f ? x : (__expf(x)-1.0f);
      float z=hsum(cB[r]); yfB[r]= z>0.0f ? z : (__expf(z)-1.0f);
    }
    uA[rg]=pack4(yfA);
    uB[rg]=pack4(yfB);
    __syncwarp();                    // hid visible

    // ================= MEAN + STD fused: one activation read serves both ======
    ull mA[4], mB[4], sA2[4], sB2[4];
#pragma unroll
    for (int r=0;r<4;r++){ mA[r]=0ull; mB[r]=0ull; sA2[r]=0ull; sB2[r]=0ull; }
#pragma unroll
    for (int p=0;p<9;p++){
      ulonglong2 xa = uA[p];
      ulonglong2 xb = uB[p];
#pragma unroll
      for (int r=0;r<4;r++){
        ulonglong2 wm = mnw[r*9 + p];
        ulonglong2 ws = sdw[r*9 + p];
        mA[r]=fma2(wm.x,xa.x,mA[r]);  mA[r]=fma2(wm.y,xa.y,mA[r]);
        mB[r]=fma2(wm.x,xb.x,mB[r]);  mB[r]=fma2(wm.y,xb.y,mB[r]);
        sA2[r]=fma2(ws.x,xa.x,sA2[r]); sA2[r]=fma2(ws.y,xa.y,sA2[r]);
        sB2[r]=fma2(ws.x,xb.x,sB2[r]); sB2[r]=fma2(ws.y,xb.y,sB2[r]);
      }
    }
    float ymA[4], ymB[4], ysA[4], ysB[4];
#pragma unroll
    for (int r=0;r<4;r++){
      ymA[r]=hsum(mA[r]);  ymB[r]=hsum(mB[r]);
      ysA[r]=softplus_fast(hsum(sA2[r]))+1e-5f;
      ysB[r]=softplus_fast(hsum(sB2[r]))+1e-5f;
    }

    // outputs: my 4 rows of mean and std for both elements (STG.128, coalesced)
    float* oA = out + ((size_t)t*B + gA)*64 + rg*4;
    float* oB = out + ((size_t)t*B + gB)*64 + rg*4;
    { float4 f; f.x=ymA[0]; f.y=ymA[1]; f.z=ymA[2]; f.w=ymA[3]; *(float4*)oA = f; }
    { float4 f; f.x=ysA[0]; f.y=ysA[1]; f.z=ysA[2]; f.w=ysA[3]; *(float4*)(oA+32) = f; }
    { float4 f; f.x=ymB[0]; f.y=ymB[1]; f.z=ymB[2]; f.w=ymB[3]; *(float4*)oB = f; }
    { float4 f; f.x=ysB[0]; f.y=ysB[1]; f.z=ysB[2]; f.w=ysB[3]; *(float4*)(oB+32) = f; }

    // mean becomes next-step s (chunks 9..16 of the NH stream)
    vA[9+rg]=pack4(ymA);
    vB[9+rg]=pack4(ymB);

    // commit prefetched actions
    aA[0]=nA0.u.x; aA[1]=nA0.u.y; aA[2]=nA1.u.x; aA[3]=nA1.u.y;
    aB[0]=nB0.u.x; aB[1]=nB0.u.y; aB[2]=nB1.u.x; aB[3]=nB1.u.y;
    __syncwarp();                    // s visible for next step
  }
}

extern "C" void kernel_launch(void* const* d_in, const int* in_sizes, int n_in,
                              void* d_out, int out_size) {
  const float* s0      = (const float*)d_in[0];
  const float* h0      = (const float*)d_in[1];
  const float* actions = (const float*)d_in[2];
  const float* W_ih    = (const float*)d_in[3];
  const float* W_hh    = (const float*)d_in[4];
  const float* b_ih    = (const float*)d_in[5];
  const float* b_hh    = (const float*)d_in[6];
  const float* fc1_w   = (const float*)d_in[7];
  const float* fc1_b   = (const float*)d_in[8];
  const float* mean_w  = (const float*)d_in[9];
  const float* mean_b  = (const float*)d_in[10];
  const float* std_w   = (const float*)d_in[11];
  const float* std_b   = (const float*)d_in[12];
  float* out = (float*)d_out;

  int B = in_sizes[0] / 32;                 // s0 is [B, 32]
  int T = in_sizes[2] / (B * 8);            // actions is [B, T, 8]
  int n_steps = out_size / (B * 64);        // out is [n_steps, B, 64]
  if (n_steps > T) n_steps = T;

  cudaFuncSetAttribute(rssm_kernel, cudaFuncAttributePreferredSharedMemoryCarveout, 100);

  rssm_kernel<<<B/16, 64>>>(s0, h0, actions, W_ih, W_hh, b_ih, b_hh,
                            fc1_w, fc1_b, mean_w, mean_b, std_w, std_b,
                            out, B, T, n_steps);
}